// round 14
// baseline (speedup 1.0000x reference)
#include <cuda_runtime.h>
#include <cuda_bf16.h>
#include <cuda_fp16.h>
#include <math.h>
#include <stdint.h>

// ============================================================================
// LocalAttention, split-precision warp MMA.
//   split x,W -> hi/lo bf16
//   Q = x@Wq^T  (bf16 3-pass, fp16-unsplit epi)
//   K = x@Wk^T  (bf16 3-pass, fp16 hi/lo epi)
//   Vt = Wv@x^T (bf16 3-pass, fp16 hi/lo epi)
//   attn = softmax(mask ? -1e9 : Q@K^T*s)  (fp16 2-pass, mask epi; fp32)
//   softmax emits P as single fp16
//   cntx = P @ Vt^T  (fp16 2-pass)
// Output: [cntx (N*D) | attn (N*N)].  Mask is int32.
// ============================================================================

#define AN 8192
#define AD 512

// ---- device-global scratch ----
__device__ __nv_bfloat16 g_xh [(size_t)AN * AD], g_xl [(size_t)AN * AD];
__device__ __nv_bfloat16 g_Wqh[(size_t)AD * AD], g_Wql[(size_t)AD * AD];
__device__ __nv_bfloat16 g_Wkh[(size_t)AD * AD], g_Wkl[(size_t)AD * AD];
__device__ __nv_bfloat16 g_Wvh[(size_t)AD * AD], g_Wvl[(size_t)AD * AD];
__device__ __half        g_Qf [(size_t)AN * AD];
__device__ __half        g_Kfh[(size_t)AN * AD], g_Kfl[(size_t)AN * AD];
__device__ __half        g_Vth[(size_t)AD * AN], g_Vtl[(size_t)AD * AN];
__device__ __half        g_P  [(size_t)AN * (size_t)AN];
__device__ float         g_S  [(size_t)AN * (size_t)AN];   // fallback attn scratch

// ---------------------------------------------------------------------------
// helpers
// ---------------------------------------------------------------------------
__device__ __forceinline__ uint32_t smem_u32(const void* p) {
    uint32_t a;
    asm("{ .reg .u64 t; cvta.to.shared.u64 t, %1; cvt.u32.u64 %0, t; }"
        : "=r"(a) : "l"(p));
    return a;
}
__device__ __forceinline__ void cp16(uint32_t dst, const void* src) {
    asm volatile("cp.async.cg.shared.global [%0], [%1], 16;" :: "r"(dst), "l"(src));
}
#define CP_COMMIT() asm volatile("cp.async.commit_group;" ::: "memory")
#define CP_WAIT(N)  asm volatile("cp.async.wait_group %0;" :: "n"(N) : "memory")

__device__ __forceinline__ void ldsm_x4(uint32_t* r, uint32_t addr) {
    asm volatile("ldmatrix.sync.aligned.m8n8.x4.shared.b16 {%0,%1,%2,%3}, [%4];"
                 : "=r"(r[0]), "=r"(r[1]), "=r"(r[2]), "=r"(r[3]) : "r"(addr));
}
__device__ __forceinline__ void mma16816(float* d, const uint32_t* a, const uint32_t* b) {
    asm volatile(
        "mma.sync.aligned.m16n8k16.row.col.f32.bf16.bf16.f32 "
        "{%0,%1,%2,%3}, {%4,%5,%6,%7}, {%8,%9}, {%0,%1,%2,%3};"
        : "+f"(d[0]), "+f"(d[1]), "+f"(d[2]), "+f"(d[3])
        : "r"(a[0]), "r"(a[1]), "r"(a[2]), "r"(a[3]), "r"(b[0]), "r"(b[1]));
}
__device__ __forceinline__ void mma16816h(float* d, const uint32_t* a, const uint32_t* b) {
    asm volatile(
        "mma.sync.aligned.m16n8k16.row.col.f32.f16.f16.f32 "
        "{%0,%1,%2,%3}, {%4,%5,%6,%7}, {%8,%9}, {%0,%1,%2,%3};"
        : "+f"(d[0]), "+f"(d[1]), "+f"(d[2]), "+f"(d[3])
        : "r"(a[0]), "r"(a[1]), "r"(a[2]), "r"(a[3]), "r"(b[0]), "r"(b[1]));
}
__device__ __forceinline__ void split1(float v, __nv_bfloat16& h, __nv_bfloat16& l) {
    h = __float2bfloat16_rn(v);
    l = __float2bfloat16_rn(v - __bfloat162float(h));
}
__device__ __forceinline__ void split1h(float v, __half& h, __half& l) {
    h = __float2half_rn(v);
    l = __float2half_rn(v - __half2float(h));
}

// 128B-row swizzle: 16B chunks c in 0..7, phys chunk = c ^ (row & 7).
__device__ __forceinline__ uint32_t swz(uint32_t row, uint32_t c) {
    return row * 128 + ((c ^ (row & 7)) << 4);
}

// ---------------------------------------------------------------------------
// split kernel: fp32 -> (hi, lo) bf16
// ---------------------------------------------------------------------------
__global__ __launch_bounds__(256)
void split_f32(const float* __restrict__ in, __nv_bfloat16* __restrict__ hi,
               __nv_bfloat16* __restrict__ lo, int n4)
{
    int i = blockIdx.x * 256 + threadIdx.x;
    if (i >= n4) return;
    float4 v = *(const float4*)(in + (size_t)i * 4);
    __nv_bfloat16 h0, h1, h2, h3, l0, l1, l2, l3;
    split1(v.x, h0, l0); split1(v.y, h1, l1);
    split1(v.z, h2, l2); split1(v.w, h3, l3);
    *(__nv_bfloat162*)(hi + (size_t)i * 4)     = __nv_bfloat162(h0, h1);
    *(__nv_bfloat162*)(hi + (size_t)i * 4 + 2) = __nv_bfloat162(h2, h3);
    *(__nv_bfloat162*)(lo + (size_t)i * 4)     = __nv_bfloat162(l0, l1);
    *(__nv_bfloat162*)(lo + (size_t)i * 4 + 2) = __nv_bfloat162(l2, l3);
}

// ---------------------------------------------------------------------------
// NT split-bf16 GEMM (3-pass): C = (Ah+Al)(Bh+Bl)^T.  Block 128x256x64,
// 512 threads, warp tile 32x64, 2-stage cp.async.
// EPI: 3 = split-fp16 out (Fhi/Flo), 4 = unsplit fp16 out (Fhi)
// ---------------------------------------------------------------------------
#define A_MAT  (128 * 128)
#define B_MAT  (256 * 128)
#define STAGEB (2 * A_MAT + 2 * B_MAT)     // 98304 B
#define SMEM_TOT (2 * STAGEB)              // 196608 B

template <int EPI>
__global__ __launch_bounds__(512)
void hgemm_nt(const __nv_bfloat16* __restrict__ Ah, const __nv_bfloat16* __restrict__ Al,
              const __nv_bfloat16* __restrict__ Bh, const __nv_bfloat16* __restrict__ Bl,
              int M, int Nn, int K,
              __half* __restrict__ Fhi, __half* __restrict__ Flo)
{
    extern __shared__ char smem[];
    const uint32_t sb = smem_u32(smem);
    const int tid = threadIdx.x;
    const int wid = tid >> 5, lid = tid & 31;
    const int mBase = blockIdx.y * 128;
    const int nBase = blockIdx.x * 256;
    const int mW = (wid & 3) * 32;
    const int nW = (wid >> 2) * 64;

    const __nv_bfloat16* gA[2] = { Ah + (size_t)mBase * K, Al + (size_t)mBase * K };
    const __nv_bfloat16* gB[2] = { Bh + (size_t)nBase * K, Bl + (size_t)nBase * K };

    float acc[2][8][4];
#pragma unroll
    for (int i = 0; i < 2; i++)
#pragma unroll
        for (int j = 0; j < 8; j++)
#pragma unroll
            for (int v = 0; v < 4; v++) acc[i][j][v] = 0.f;

    const int ntiles = K / 64;

    auto load_tile = [&](int kt, int s) {
        const uint32_t st = sb + s * STAGEB;
#pragma unroll
        for (int j = 0; j < 2; ++j) {
            int slot = tid + j * 512;
            int row = slot >> 3, c = slot & 7;
            size_t go = (size_t)row * K + kt * 64 + c * 8;
            uint32_t so = swz(row, c);
            cp16(st + 0 * A_MAT + so, gA[0] + go);
            cp16(st + 1 * A_MAT + so, gA[1] + go);
        }
#pragma unroll
        for (int j = 0; j < 4; ++j) {
            int slot = tid + j * 512;
            int row = slot >> 3, c = slot & 7;
            size_t go = (size_t)row * K + kt * 64 + c * 8;
            uint32_t so = swz(row, c);
            cp16(st + 2 * A_MAT + so,         gB[0] + go);
            cp16(st + 2 * A_MAT + B_MAT + so, gB[1] + go);
        }
        CP_COMMIT();
    };

    load_tile(0, 0);

    for (int kt = 0; kt < ntiles; ++kt) {
        if (kt + 1 < ntiles) {
            load_tile(kt + 1, (kt + 1) & 1);
            CP_WAIT(1);
        } else {
            CP_WAIT(0);
        }
        __syncthreads();

        const uint32_t st = sb + (kt & 1) * STAGEB;

#pragma unroll
        for (int s = 0; s < 4; ++s) {
            uint32_t ah[2][4], al[2][4];
            const uint32_t cA = s * 2 + (lid >> 4);
#pragma unroll
            for (int f = 0; f < 2; ++f) {
                uint32_t ra = st + swz(mW + f * 16 + (lid & 15), cA);
                ldsm_x4(ah[f], ra);
                ldsm_x4(al[f], ra + A_MAT);
            }
            const uint32_t rowB = ((lid >> 4) * 8) + (lid & 7);
            const uint32_t cB = s * 2 + ((lid >> 3) & 1);
#pragma unroll
            for (int half = 0; half < 2; ++half) {
                uint32_t bh[4][2], bl[4][2];
#pragma unroll
                for (int f = 0; f < 2; ++f) {
                    uint32_t rb = st + 2 * A_MAT +
                                  swz(nW + half * 32 + f * 16 + rowB, cB);
                    ldsm_x4(&bh[2 * f][0], rb);
                    ldsm_x4(&bl[2 * f][0], rb + B_MAT);
                }
#pragma unroll
                for (int mf = 0; mf < 2; ++mf)
#pragma unroll
                    for (int nf = 0; nf < 4; ++nf) {
                        float* d = acc[mf][half * 4 + nf];
                        mma16816(d, ah[mf], bh[nf]);
                        mma16816(d, ah[mf], bl[nf]);
                        mma16816(d, al[mf], bh[nf]);
                    }
            }
        }
        __syncthreads();
    }

    // ---- epilogue ----
    const int r0b = mBase + mW + (lid >> 2);
    const int c0b = nBase + nW + (lid & 3) * 2;
#pragma unroll
    for (int mf = 0; mf < 2; ++mf) {
#pragma unroll
        for (int nf = 0; nf < 8; ++nf) {
            const float* d = acc[mf][nf];
#pragma unroll
            for (int h = 0; h < 2; ++h) {
                int row = r0b + mf * 16 + h * 8;
                int col = c0b + nf * 8;
                size_t o = (size_t)row * Nn + col;
                float v0 = d[h * 2 + 0], v1 = d[h * 2 + 1];
                if (EPI == 3) {
                    __half h0, h1, l0, l1;
                    split1h(v0, h0, l0); split1h(v1, h1, l1);
                    *(__half2*)(Fhi + o) = __halves2half2(h0, h1);
                    *(__half2*)(Flo + o) = __halves2half2(l0, l1);
                } else {
                    *(__half2*)(Fhi + o) = __floats2half2_rn(v0, v1);
                }
            }
        }
    }
}

// ---------------------------------------------------------------------------
// NT fp16 2-pass GEMM: C[M,Nn] = A[M,K] * (Bh+Bl)[Nn,K]^T, fp32 out.
// A unsplit fp16. Block 128x256x64, 512 threads, warp tile 32x64, 2-stage.
// EPI: 1 = mask+scale fp32, 2 = plain fp32
// ---------------------------------------------------------------------------
#define STAGE2 (A_MAT + 2 * B_MAT)         // 81920 B (A|Bh|Bl)
#define SMEM2_TOT (2 * STAGE2)             // 163840 B

template <int EPI>
__global__ __launch_bounds__(512)
void hgemm2_f16(const __half* __restrict__ A,
                const __half* __restrict__ Bh, const __half* __restrict__ Bl,
                int M, int Nn, int K, float* __restrict__ Cf,
                const int* __restrict__ mask, float scale)
{
    extern __shared__ char smem[];
    const uint32_t sb = smem_u32(smem);
    const int tid = threadIdx.x;
    const int wid = tid >> 5, lid = tid & 31;
    const int mBase = blockIdx.y * 128;
    const int nBase = blockIdx.x * 256;
    const int mW = (wid & 3) * 32;
    const int nW = (wid >> 2) * 64;

    const __half* gA = A + (size_t)mBase * K;
    const __half* gB[2] = { Bh + (size_t)nBase * K, Bl + (size_t)nBase * K };

    float acc[2][8][4];
#pragma unroll
    for (int i = 0; i < 2; i++)
#pragma unroll
        for (int j = 0; j < 8; j++)
#pragma unroll
            for (int v = 0; v < 4; v++) acc[i][j][v] = 0.f;

    const int ntiles = K / 64;

    auto load_tile = [&](int kt, int s) {
        const uint32_t st = sb + s * STAGE2;
#pragma unroll
        for (int j = 0; j < 2; ++j) {
            int slot = tid + j * 512;
            int row = slot >> 3, c = slot & 7;
            size_t go = (size_t)row * K + kt * 64 + c * 8;
            cp16(st + swz(row, c), gA + go);
        }
#pragma unroll
        for (int j = 0; j < 4; ++j) {
            int slot = tid + j * 512;
            int row = slot >> 3, c = slot & 7;
            size_t go = (size_t)row * K + kt * 64 + c * 8;
            uint32_t so = swz(row, c);
            cp16(st + A_MAT + so,         gB[0] + go);
            cp16(st + A_MAT + B_MAT + so, gB[1] + go);
        }
        CP_COMMIT();
    };

    load_tile(0, 0);

    for (int kt = 0; kt < ntiles; ++kt) {
        if (kt + 1 < ntiles) {
            load_tile(kt + 1, (kt + 1) & 1);
            CP_WAIT(1);
        } else {
            CP_WAIT(0);
        }
        __syncthreads();

        const uint32_t st = sb + (kt & 1) * STAGE2;

#pragma unroll
        for (int s = 0; s < 4; ++s) {
            uint32_t ah[2][4];
            const uint32_t cA = s * 2 + (lid >> 4);
#pragma unroll
            for (int f = 0; f < 2; ++f)
                ldsm_x4(ah[f], st + swz(mW + f * 16 + (lid & 15), cA));

            const uint32_t rowB = ((lid >> 4) * 8) + (lid & 7);
            const uint32_t cB = s * 2 + ((lid >> 3) & 1);
#pragma unroll
            for (int half = 0; half < 2; ++half) {
                uint32_t bh[4][2], bl[4][2];
#pragma unroll
                for (int f = 0; f < 2; ++f) {
                    uint32_t rb = st + A_MAT +
                                  swz(nW + half * 32 + f * 16 + rowB, cB);
                    ldsm_x4(&bh[2 * f][0], rb);
                    ldsm_x4(&bl[2 * f][0], rb + B_MAT);
                }
#pragma unroll
                for (int mf = 0; mf < 2; ++mf)
#pragma unroll
                    for (int nf = 0; nf < 4; ++nf) {
                        float* d = acc[mf][half * 4 + nf];
                        mma16816h(d, ah[mf], bh[nf]);
                        mma16816h(d, ah[mf], bl[nf]);
                    }
            }
        }
        __syncthreads();
    }

    const int r0b = mBase + mW + (lid >> 2);
    const int c0b = nBase + nW + (lid & 3) * 2;
#pragma unroll
    for (int mf = 0; mf < 2; ++mf)
#pragma unroll
        for (int nf = 0; nf < 8; ++nf) {
            const float* d = acc[mf][nf];
#pragma unroll
            for (int h = 0; h < 2; ++h) {
                int row = r0b + mf * 16 + h * 8;
                int col = c0b + nf * 8;
                size_t o = (size_t)row * Nn + col;
                float v0 = d[h * 2 + 0], v1 = d[h * 2 + 1];
                if (EPI == 1) {
                    int2 mv = *(const int2*)(mask + o);
                    float2 w;
                    w.x = mv.x ? -1e9f : v0 * scale;
                    w.y = mv.y ? -1e9f : v1 * scale;
                    *(float2*)(Cf + o) = w;
                } else {
                    *(float2*)(Cf + o) = make_float2(v0, v1);
                }
            }
        }
}

// ---------------------------------------------------------------------------
// Row softmax (in place, fp32) + emit P as single fp16.
// ---------------------------------------------------------------------------
__global__ __launch_bounds__(256)
void softmax_rows(float* __restrict__ S, __half* __restrict__ P, int n)
{
    extern __shared__ float row[];
    __shared__ float red[33];

    const int tid = threadIdx.x;
    float* p = S + (size_t)blockIdx.x * n;
    __half* ph = P + (size_t)blockIdx.x * n;

    float m = -INFINITY;
    for (int i = tid * 4; i < n; i += 1024) {
        float4 v = *(const float4*)(p + i);
        *(float4*)(row + i) = v;
        m = fmaxf(m, fmaxf(fmaxf(v.x, v.y), fmaxf(v.z, v.w)));
    }
#pragma unroll
    for (int o = 16; o; o >>= 1) m = fmaxf(m, __shfl_xor_sync(~0u, m, o));
    if ((tid & 31) == 0) red[tid >> 5] = m;
    __syncthreads();
    if (tid < 32) {
        float v = (tid < 8) ? red[tid] : -INFINITY;
#pragma unroll
        for (int o = 4; o; o >>= 1) v = fmaxf(v, __shfl_xor_sync(~0u, v, o));
        if (tid == 0) red[32] = v;
    }
    __syncthreads();
    m = red[32];

    float s = 0.f;
    for (int i = tid * 4; i < n; i += 1024) {
        float4 v = *(float4*)(row + i);
        v.x = __expf(v.x - m); v.y = __expf(v.y - m);
        v.z = __expf(v.z - m); v.w = __expf(v.w - m);
        s += (v.x + v.y) + (v.z + v.w);
        *(float4*)(row + i) = v;
    }
    __syncthreads();
#pragma unroll
    for (int o = 16; o; o >>= 1) s += __shfl_xor_sync(~0u, s, o);
    if ((tid & 31) == 0) red[tid >> 5] = s;
    __syncthreads();
    if (tid < 32) {
        float v = (tid < 8) ? red[tid] : 0.f;
#pragma unroll
        for (int o = 4; o; o >>= 1) v += __shfl_xor_sync(~0u, v, o);
        if (tid == 0) red[32] = v;
    }
    __syncthreads();
    const float inv = 1.f / red[32];

    for (int i = tid * 4; i < n; i += 1024) {
        float4 v = *(float4*)(row + i);
        v.x *= inv; v.y *= inv; v.z *= inv; v.w *= inv;
        *(float4*)(p + i) = v;
        *(__half2*)(ph + i)     = __floats2half2_rn(v.x, v.y);
        *(__half2*)(ph + i + 2) = __floats2half2_rn(v.z, v.w);
    }
}

// ---------------------------------------------------------------------------
// Launch
// ---------------------------------------------------------------------------
extern "C" void kernel_launch(void* const* d_in, const int* in_sizes, int n_in,
                              void* d_out, int out_size)
{
    const float* x    = (const float*)d_in[0];
    const int*   mask = (const int*)d_in[1];
    const float* Wq   = (const float*)d_in[2];
    const float* Wk   = (const float*)d_in[3];
    const float* Wv   = (const float*)d_in[4];
    float* out = (float*)d_out;

    __nv_bfloat16 *xh, *xl, *Wqh, *Wql, *Wkh, *Wkl, *Wvh, *Wvl;
    __half *Qf, *Kfh, *Kfl, *Vth, *Vtl, *P;
    cudaGetSymbolAddress((void**)&xh,  g_xh);  cudaGetSymbolAddress((void**)&xl,  g_xl);
    cudaGetSymbolAddress((void**)&Wqh, g_Wqh); cudaGetSymbolAddress((void**)&Wql, g_Wql);
    cudaGetSymbolAddress((void**)&Wkh, g_Wkh); cudaGetSymbolAddress((void**)&Wkl, g_Wkl);
    cudaGetSymbolAddress((void**)&Wvh, g_Wvh); cudaGetSymbolAddress((void**)&Wvl, g_Wvl);
    cudaGetSymbolAddress((void**)&Qf,  g_Qf);
    cudaGetSymbolAddress((void**)&Kfh, g_Kfh); cudaGetSymbolAddress((void**)&Kfl, g_Kfl);
    cudaGetSymbolAddress((void**)&Vth, g_Vth); cudaGetSymbolAddress((void**)&Vtl, g_Vtl);
    cudaGetSymbolAddress((void**)&P,   g_P);

    const size_t nd = (size_t)AN * AD;
    const size_t nn = (size_t)AN * AN;
    float* cntx = out;
    float* attn = out + nd;
    if ((size_t)out_size < nd + nn)
        cudaGetSymbolAddress((void**)&attn, g_S);

    const float scale = 1.0f / sqrtf((float)AD);

    cudaFuncSetAttribute(hgemm_nt<3>,   cudaFuncAttributeMaxDynamicSharedMemorySize, SMEM_TOT);
    cudaFuncSetAttribute(hgemm_nt<4>,   cudaFuncAttributeMaxDynamicSharedMemorySize, SMEM_TOT);
    cudaFuncSetAttribute(hgemm2_f16<1>, cudaFuncAttributeMaxDynamicSharedMemorySize, SMEM2_TOT);
    cudaFuncSetAttribute(hgemm2_f16<2>, cudaFuncAttributeMaxDynamicSharedMemorySize, SMEM2_TOT);

    // 1) split inputs (bf16 hi/lo)
    split_f32<<<(AN * AD / 4 + 255) / 256, 256>>>(x,  xh,  xl,  AN * AD / 4);
    split_f32<<<(AD * AD / 4 + 255) / 256, 256>>>(Wq, Wqh, Wql, AD * AD / 4);
    split_f32<<<(AD * AD / 4 + 255) / 256, 256>>>(Wk, Wkh, Wkl, AD * AD / 4);
    split_f32<<<(AD * AD / 4 + 255) / 256, 256>>>(Wv, Wvh, Wvl, AD * AD / 4);

    // 2) projections (bf16 3-pass, fp16 outputs)
    dim3 gP(AD / 256, AN / 128);
    hgemm_nt<4><<<gP, 512, SMEM_TOT>>>(xh, xl, Wqh, Wql, AN, AD, AD, Qf, nullptr);
    hgemm_nt<3><<<gP, 512, SMEM_TOT>>>(xh, xl, Wkh, Wkl, AN, AD, AD, Kfh, Kfl);
    dim3 gV(AN / 256, AD / 128);
    hgemm_nt<3><<<gV, 512, SMEM_TOT>>>(Wvh, Wvl, xh, xl, AD, AN, AD, Vth, Vtl);

    // 3) scores: fp16 2-pass (Q unsplit, K hi/lo), mask epilogue
    dim3 gS(AN / 256, AN / 128);
    hgemm2_f16<1><<<gS, 512, SMEM2_TOT>>>(Qf, Kfh, Kfl, AN, AN, AD,
                                          attn, mask, scale);

    // 4) softmax (+ fp16 P)
    softmax_rows<<<AN, 256, AN * sizeof(float)>>>(attn, P, AN);

    // 5) context: fp16 2-pass
    dim3 gC(AD / 256, AN / 128);
    hgemm2_f16<2><<<gC, 512, SMEM2_TOT>>>(P, Vth, Vtl, AN, AD, AN,
                                          cntx, nullptr, 1.f);
}

// round 15
// speedup vs baseline: 1.5154x; 1.5154x over previous
#include <cuda_runtime.h>
#include <cuda_bf16.h>
#include <cuda_fp16.h>
#include <math.h>
#include <stdint.h>

// ============================================================================
// LocalAttention, split-precision warp MMA.
//   split x,W -> hi/lo bf16
//   Q = x@Wq^T  (bf16 3-pass, fp16-unsplit epi)
//   K = x@Wk^T  (bf16 3-pass, fp16 hi/lo epi)
//   Vt = Wv@x^T (bf16 3-pass, fp16 hi/lo epi)
//   attn = softmax(mask ? -1e9 : Q@K^T*s)  (fp16 2-pass, mask epi; fp32)
//   softmax emits P as single fp16
//   cntx = P @ Vt^T  (fp16 2-pass)
// Output: [cntx (N*D) | attn (N*N)].  Mask is int32.
// ============================================================================

#define AN 8192
#define AD 512

// ---- device-global scratch ----
__device__ __nv_bfloat16 g_xh [(size_t)AN * AD], g_xl [(size_t)AN * AD];
__device__ __nv_bfloat16 g_Wqh[(size_t)AD * AD], g_Wql[(size_t)AD * AD];
__device__ __nv_bfloat16 g_Wkh[(size_t)AD * AD], g_Wkl[(size_t)AD * AD];
__device__ __nv_bfloat16 g_Wvh[(size_t)AD * AD], g_Wvl[(size_t)AD * AD];
__device__ __half        g_Qf [(size_t)AN * AD];
__device__ __half        g_Kfh[(size_t)AN * AD], g_Kfl[(size_t)AN * AD];
__device__ __half        g_Vth[(size_t)AD * AN], g_Vtl[(size_t)AD * AN];
__device__ __half        g_P  [(size_t)AN * (size_t)AN];
__device__ float         g_S  [(size_t)AN * (size_t)AN];   // fallback attn scratch

// ---------------------------------------------------------------------------
// helpers
// ---------------------------------------------------------------------------
__device__ __forceinline__ uint32_t smem_u32(const void* p) {
    uint32_t a;
    asm("{ .reg .u64 t; cvta.to.shared.u64 t, %1; cvt.u32.u64 %0, t; }"
        : "=r"(a) : "l"(p));
    return a;
}
__device__ __forceinline__ void cp16(uint32_t dst, const void* src) {
    asm volatile("cp.async.cg.shared.global [%0], [%1], 16;" :: "r"(dst), "l"(src));
}
#define CP_COMMIT() asm volatile("cp.async.commit_group;" ::: "memory")
#define CP_WAIT(N)  asm volatile("cp.async.wait_group %0;" :: "n"(N) : "memory")

__device__ __forceinline__ void ldsm_x4(uint32_t* r, uint32_t addr) {
    asm volatile("ldmatrix.sync.aligned.m8n8.x4.shared.b16 {%0,%1,%2,%3}, [%4];"
                 : "=r"(r[0]), "=r"(r[1]), "=r"(r[2]), "=r"(r[3]) : "r"(addr));
}
__device__ __forceinline__ void mma16816(float* d, const uint32_t* a, const uint32_t* b) {
    asm volatile(
        "mma.sync.aligned.m16n8k16.row.col.f32.bf16.bf16.f32 "
        "{%0,%1,%2,%3}, {%4,%5,%6,%7}, {%8,%9}, {%0,%1,%2,%3};"
        : "+f"(d[0]), "+f"(d[1]), "+f"(d[2]), "+f"(d[3])
        : "r"(a[0]), "r"(a[1]), "r"(a[2]), "r"(a[3]), "r"(b[0]), "r"(b[1]));
}
__device__ __forceinline__ void mma16816h(float* d, const uint32_t* a, const uint32_t* b) {
    asm volatile(
        "mma.sync.aligned.m16n8k16.row.col.f32.f16.f16.f32 "
        "{%0,%1,%2,%3}, {%4,%5,%6,%7}, {%8,%9}, {%0,%1,%2,%3};"
        : "+f"(d[0]), "+f"(d[1]), "+f"(d[2]), "+f"(d[3])
        : "r"(a[0]), "r"(a[1]), "r"(a[2]), "r"(a[3]), "r"(b[0]), "r"(b[1]));
}
__device__ __forceinline__ void split1(float v, __nv_bfloat16& h, __nv_bfloat16& l) {
    h = __float2bfloat16_rn(v);
    l = __float2bfloat16_rn(v - __bfloat162float(h));
}
__device__ __forceinline__ void split1h(float v, __half& h, __half& l) {
    h = __float2half_rn(v);
    l = __float2half_rn(v - __half2float(h));
}

// 128B-row swizzle: 16B chunks c in 0..7, phys chunk = c ^ (row & 7).
__device__ __forceinline__ uint32_t swz(uint32_t row, uint32_t c) {
    return row * 128 + ((c ^ (row & 7)) << 4);
}

// ---------------------------------------------------------------------------
// split kernel: fp32 -> (hi, lo) bf16
// ---------------------------------------------------------------------------
__global__ __launch_bounds__(256)
void split_f32(const float* __restrict__ in, __nv_bfloat16* __restrict__ hi,
               __nv_bfloat16* __restrict__ lo, int n4)
{
    int i = blockIdx.x * 256 + threadIdx.x;
    if (i >= n4) return;
    float4 v = *(const float4*)(in + (size_t)i * 4);
    __nv_bfloat16 h0, h1, h2, h3, l0, l1, l2, l3;
    split1(v.x, h0, l0); split1(v.y, h1, l1);
    split1(v.z, h2, l2); split1(v.w, h3, l3);
    *(__nv_bfloat162*)(hi + (size_t)i * 4)     = __nv_bfloat162(h0, h1);
    *(__nv_bfloat162*)(hi + (size_t)i * 4 + 2) = __nv_bfloat162(h2, h3);
    *(__nv_bfloat162*)(lo + (size_t)i * 4)     = __nv_bfloat162(l0, l1);
    *(__nv_bfloat162*)(lo + (size_t)i * 4 + 2) = __nv_bfloat162(l2, l3);
}

// ---------------------------------------------------------------------------
// NT split-bf16 GEMM (3-pass): C = (Ah+Al)(Bh+Bl)^T.  Block 128x256x64,
// 512 threads, warp tile 32x64, 2-stage cp.async.
// EPI: 3 = split-fp16 out (Fhi/Flo), 4 = unsplit fp16 out (Fhi)
// ---------------------------------------------------------------------------
#define A_MAT  (128 * 128)
#define B_MAT  (256 * 128)
#define STAGEB (2 * A_MAT + 2 * B_MAT)     // 98304 B
#define SMEM_TOT (2 * STAGEB)              // 196608 B

template <int EPI>
__global__ __launch_bounds__(512)
void hgemm_nt(const __nv_bfloat16* __restrict__ Ah, const __nv_bfloat16* __restrict__ Al,
              const __nv_bfloat16* __restrict__ Bh, const __nv_bfloat16* __restrict__ Bl,
              int M, int Nn, int K,
              __half* __restrict__ Fhi, __half* __restrict__ Flo)
{
    extern __shared__ char smem[];
    const uint32_t sb = smem_u32(smem);
    const int tid = threadIdx.x;
    const int wid = tid >> 5, lid = tid & 31;
    const int mBase = blockIdx.y * 128;
    const int nBase = blockIdx.x * 256;
    const int mW = (wid & 3) * 32;
    const int nW = (wid >> 2) * 64;

    const __nv_bfloat16* gA[2] = { Ah + (size_t)mBase * K, Al + (size_t)mBase * K };
    const __nv_bfloat16* gB[2] = { Bh + (size_t)nBase * K, Bl + (size_t)nBase * K };

    float acc[2][8][4];
#pragma unroll
    for (int i = 0; i < 2; i++)
#pragma unroll
        for (int j = 0; j < 8; j++)
#pragma unroll
            for (int v = 0; v < 4; v++) acc[i][j][v] = 0.f;

    const int ntiles = K / 64;

    auto load_tile = [&](int kt, int s) {
        const uint32_t st = sb + s * STAGEB;
#pragma unroll
        for (int j = 0; j < 2; ++j) {
            int slot = tid + j * 512;
            int row = slot >> 3, c = slot & 7;
            size_t go = (size_t)row * K + kt * 64 + c * 8;
            uint32_t so = swz(row, c);
            cp16(st + 0 * A_MAT + so, gA[0] + go);
            cp16(st + 1 * A_MAT + so, gA[1] + go);
        }
#pragma unroll
        for (int j = 0; j < 4; ++j) {
            int slot = tid + j * 512;
            int row = slot >> 3, c = slot & 7;
            size_t go = (size_t)row * K + kt * 64 + c * 8;
            uint32_t so = swz(row, c);
            cp16(st + 2 * A_MAT + so,         gB[0] + go);
            cp16(st + 2 * A_MAT + B_MAT + so, gB[1] + go);
        }
        CP_COMMIT();
    };

    load_tile(0, 0);

    for (int kt = 0; kt < ntiles; ++kt) {
        if (kt + 1 < ntiles) {
            load_tile(kt + 1, (kt + 1) & 1);
            CP_WAIT(1);
        } else {
            CP_WAIT(0);
        }
        __syncthreads();

        const uint32_t st = sb + (kt & 1) * STAGEB;

#pragma unroll
        for (int s = 0; s < 4; ++s) {
            uint32_t ah[2][4], al[2][4];
            const uint32_t cA = s * 2 + (lid >> 4);
#pragma unroll
            for (int f = 0; f < 2; ++f) {
                uint32_t ra = st + swz(mW + f * 16 + (lid & 15), cA);
                ldsm_x4(ah[f], ra);
                ldsm_x4(al[f], ra + A_MAT);
            }
            const uint32_t rowB = ((lid >> 4) * 8) + (lid & 7);
            const uint32_t cB = s * 2 + ((lid >> 3) & 1);
#pragma unroll
            for (int half = 0; half < 2; ++half) {
                uint32_t bh[4][2], bl[4][2];
#pragma unroll
                for (int f = 0; f < 2; ++f) {
                    uint32_t rb = st + 2 * A_MAT +
                                  swz(nW + half * 32 + f * 16 + rowB, cB);
                    ldsm_x4(&bh[2 * f][0], rb);
                    ldsm_x4(&bl[2 * f][0], rb + B_MAT);
                }
#pragma unroll
                for (int mf = 0; mf < 2; ++mf)
#pragma unroll
                    for (int nf = 0; nf < 4; ++nf) {
                        float* d = acc[mf][half * 4 + nf];
                        mma16816(d, ah[mf], bh[nf]);
                        mma16816(d, ah[mf], bl[nf]);
                        mma16816(d, al[mf], bh[nf]);
                    }
            }
        }
        __syncthreads();
    }

    // ---- epilogue ----
    const int r0b = mBase + mW + (lid >> 2);
    const int c0b = nBase + nW + (lid & 3) * 2;
#pragma unroll
    for (int mf = 0; mf < 2; ++mf) {
#pragma unroll
        for (int nf = 0; nf < 8; ++nf) {
            const float* d = acc[mf][nf];
#pragma unroll
            for (int h = 0; h < 2; ++h) {
                int row = r0b + mf * 16 + h * 8;
                int col = c0b + nf * 8;
                size_t o = (size_t)row * Nn + col;
                float v0 = d[h * 2 + 0], v1 = d[h * 2 + 1];
                if (EPI == 3) {
                    __half h0, h1, l0, l1;
                    split1h(v0, h0, l0); split1h(v1, h1, l1);
                    *(__half2*)(Fhi + o) = __halves2half2(h0, h1);
                    *(__half2*)(Flo + o) = __halves2half2(l0, l1);
                } else {
                    *(__half2*)(Fhi + o) = __floats2half2_rn(v0, v1);
                }
            }
        }
    }
}

// ---------------------------------------------------------------------------
// NT fp16 2-pass GEMM: C[M,Nn] = A[M,K] * (Bh+Bl)[Nn,K]^T, fp32 out.
// A unsplit fp16. Block 128x256x64, 512 threads, warp tile 32x64, 2-stage.
// EPI: 1 = mask+scale fp32, 2 = plain fp32
// ---------------------------------------------------------------------------
#define STAGE2 (A_MAT + 2 * B_MAT)         // 81920 B (A|Bh|Bl)
#define SMEM2_TOT (2 * STAGE2)             // 163840 B

template <int EPI>
__global__ __launch_bounds__(512)
void hgemm2_f16(const __half* __restrict__ A,
                const __half* __restrict__ Bh, const __half* __restrict__ Bl,
                int M, int Nn, int K, float* __restrict__ Cf,
                const int* __restrict__ mask, float scale)
{
    extern __shared__ char smem[];
    const uint32_t sb = smem_u32(smem);
    const int tid = threadIdx.x;
    const int wid = tid >> 5, lid = tid & 31;
    const int mBase = blockIdx.y * 128;
    const int nBase = blockIdx.x * 256;
    const int mW = (wid & 3) * 32;
    const int nW = (wid >> 2) * 64;

    const __half* gA = A + (size_t)mBase * K;
    const __half* gB[2] = { Bh + (size_t)nBase * K, Bl + (size_t)nBase * K };

    float acc[2][8][4];
#pragma unroll
    for (int i = 0; i < 2; i++)
#pragma unroll
        for (int j = 0; j < 8; j++)
#pragma unroll
            for (int v = 0; v < 4; v++) acc[i][j][v] = 0.f;

    const int ntiles = K / 64;

    auto load_tile = [&](int kt, int s) {
        const uint32_t st = sb + s * STAGE2;
#pragma unroll
        for (int j = 0; j < 2; ++j) {
            int slot = tid + j * 512;
            int row = slot >> 3, c = slot & 7;
            size_t go = (size_t)row * K + kt * 64 + c * 8;
            cp16(st + swz(row, c), gA + go);
        }
#pragma unroll
        for (int j = 0; j < 4; ++j) {
            int slot = tid + j * 512;
            int row = slot >> 3, c = slot & 7;
            size_t go = (size_t)row * K + kt * 64 + c * 8;
            uint32_t so = swz(row, c);
            cp16(st + A_MAT + so,         gB[0] + go);
            cp16(st + A_MAT + B_MAT + so, gB[1] + go);
        }
        CP_COMMIT();
    };

    load_tile(0, 0);

    for (int kt = 0; kt < ntiles; ++kt) {
        if (kt + 1 < ntiles) {
            load_tile(kt + 1, (kt + 1) & 1);
            CP_WAIT(1);
        } else {
            CP_WAIT(0);
        }
        __syncthreads();

        const uint32_t st = sb + (kt & 1) * STAGE2;

#pragma unroll
        for (int s = 0; s < 4; ++s) {
            uint32_t ah[2][4];
            const uint32_t cA = s * 2 + (lid >> 4);
#pragma unroll
            for (int f = 0; f < 2; ++f)
                ldsm_x4(ah[f], st + swz(mW + f * 16 + (lid & 15), cA));

            const uint32_t rowB = ((lid >> 4) * 8) + (lid & 7);
            const uint32_t cB = s * 2 + ((lid >> 3) & 1);
#pragma unroll
            for (int half = 0; half < 2; ++half) {
                uint32_t bh[4][2], bl[4][2];
#pragma unroll
                for (int f = 0; f < 2; ++f) {
                    uint32_t rb = st + A_MAT +
                                  swz(nW + half * 32 + f * 16 + rowB, cB);
                    ldsm_x4(&bh[2 * f][0], rb);
                    ldsm_x4(&bl[2 * f][0], rb + B_MAT);
                }
#pragma unroll
                for (int mf = 0; mf < 2; ++mf)
#pragma unroll
                    for (int nf = 0; nf < 4; ++nf) {
                        float* d = acc[mf][half * 4 + nf];
                        mma16816h(d, ah[mf], bh[nf]);
                        mma16816h(d, ah[mf], bl[nf]);
                    }
            }
        }
        __syncthreads();
    }

    const int r0b = mBase + mW + (lid >> 2);
    const int c0b = nBase + nW + (lid & 3) * 2;
#pragma unroll
    for (int mf = 0; mf < 2; ++mf)
#pragma unroll
        for (int nf = 0; nf < 8; ++nf) {
            const float* d = acc[mf][nf];
#pragma unroll
            for (int h = 0; h < 2; ++h) {
                int row = r0b + mf * 16 + h * 8;
                int col = c0b + nf * 8;
                size_t o = (size_t)row * Nn + col;
                float v0 = d[h * 2 + 0], v1 = d[h * 2 + 1];
                if (EPI == 1) {
                    int2 mv = *(const int2*)(mask + o);
                    float2 w;
                    w.x = mv.x ? -1e9f : v0 * scale;
                    w.y = mv.y ? -1e9f : v1 * scale;
                    *(float2*)(Cf + o) = w;
                } else {
                    *(float2*)(Cf + o) = make_float2(v0, v1);
                }
            }
        }
}

// ---------------------------------------------------------------------------
// Row softmax (in place, fp32) + emit P as single fp16.  512 threads/row.
// ---------------------------------------------------------------------------
__global__ __launch_bounds__(512)
void softmax_rows(float* __restrict__ S, __half* __restrict__ P, int n)
{
    extern __shared__ float row[];
    __shared__ float red[17];

    const int tid = threadIdx.x;
    float* p = S + (size_t)blockIdx.x * n;
    __half* ph = P + (size_t)blockIdx.x * n;

    float m = -INFINITY;
    for (int i = tid * 4; i < n; i += 2048) {
        float4 v = *(const float4*)(p + i);
        *(float4*)(row + i) = v;
        m = fmaxf(m, fmaxf(fmaxf(v.x, v.y), fmaxf(v.z, v.w)));
    }
#pragma unroll
    for (int o = 16; o; o >>= 1) m = fmaxf(m, __shfl_xor_sync(~0u, m, o));
    if ((tid & 31) == 0) red[tid >> 5] = m;
    __syncthreads();
    if (tid < 32) {
        float v = (tid < 16) ? red[tid] : -INFINITY;
#pragma unroll
        for (int o = 8; o; o >>= 1) v = fmaxf(v, __shfl_xor_sync(~0u, v, o));
        if (tid == 0) red[16] = v;
    }
    __syncthreads();
    m = red[16];

    float s = 0.f;
    for (int i = tid * 4; i < n; i += 2048) {
        float4 v = *(float4*)(row + i);
        v.x = __expf(v.x - m); v.y = __expf(v.y - m);
        v.z = __expf(v.z - m); v.w = __expf(v.w - m);
        s += (v.x + v.y) + (v.z + v.w);
        *(float4*)(row + i) = v;
    }
    __syncthreads();
#pragma unroll
    for (int o = 16; o; o >>= 1) s += __shfl_xor_sync(~0u, s, o);
    if ((tid & 31) == 0) red[tid >> 5] = s;
    __syncthreads();
    if (tid < 32) {
        float v = (tid < 16) ? red[tid] : 0.f;
#pragma unroll
        for (int o = 8; o; o >>= 1) v += __shfl_xor_sync(~0u, v, o);
        if (tid == 0) red[16] = v;
    }
    __syncthreads();
    const float inv = 1.f / red[16];

    for (int i = tid * 4; i < n; i += 2048) {
        float4 v = *(float4*)(row + i);
        v.x *= inv; v.y *= inv; v.z *= inv; v.w *= inv;
        *(float4*)(p + i) = v;
        *(__half2*)(ph + i)     = __floats2half2_rn(v.x, v.y);
        *(__half2*)(ph + i + 2) = __floats2half2_rn(v.z, v.w);
    }
}

// ---------------------------------------------------------------------------
// Launch
// ---------------------------------------------------------------------------
extern "C" void kernel_launch(void* const* d_in, const int* in_sizes, int n_in,
                              void* d_out, int out_size)
{
    const float* x    = (const float*)d_in[0];
    const int*   mask = (const int*)d_in[1];
    const float* Wq   = (const float*)d_in[2];
    const float* Wk   = (const float*)d_in[3];
    const float* Wv   = (const float*)d_in[4];
    float* out = (float*)d_out;

    __nv_bfloat16 *xh, *xl, *Wqh, *Wql, *Wkh, *Wkl, *Wvh, *Wvl;
    __half *Qf, *Kfh, *Kfl, *Vth, *Vtl, *P;
    cudaGetSymbolAddress((void**)&xh,  g_xh);  cudaGetSymbolAddress((void**)&xl,  g_xl);
    cudaGetSymbolAddress((void**)&Wqh, g_Wqh); cudaGetSymbolAddress((void**)&Wql, g_Wql);
    cudaGetSymbolAddress((void**)&Wkh, g_Wkh); cudaGetSymbolAddress((void**)&Wkl, g_Wkl);
    cudaGetSymbolAddress((void**)&Wvh, g_Wvh); cudaGetSymbolAddress((void**)&Wvl, g_Wvl);
    cudaGetSymbolAddress((void**)&Qf,  g_Qf);
    cudaGetSymbolAddress((void**)&Kfh, g_Kfh); cudaGetSymbolAddress((void**)&Kfl, g_Kfl);
    cudaGetSymbolAddress((void**)&Vth, g_Vth); cudaGetSymbolAddress((void**)&Vtl, g_Vtl);
    cudaGetSymbolAddress((void**)&P,   g_P);

    const size_t nd = (size_t)AN * AD;
    const size_t nn = (size_t)AN * AN;
    float* cntx = out;
    float* attn = out + nd;
    if ((size_t)out_size < nd + nn)
        cudaGetSymbolAddress((void**)&attn, g_S);

    const float scale = 1.0f / sqrtf((float)AD);

    cudaFuncSetAttribute(hgemm_nt<3>,   cudaFuncAttributeMaxDynamicSharedMemorySize, SMEM_TOT);
    cudaFuncSetAttribute(hgemm_nt<4>,   cudaFuncAttributeMaxDynamicSharedMemorySize, SMEM_TOT);
    cudaFuncSetAttribute(hgemm2_f16<1>, cudaFuncAttributeMaxDynamicSharedMemorySize, SMEM2_TOT);
    cudaFuncSetAttribute(hgemm2_f16<2>, cudaFuncAttributeMaxDynamicSharedMemorySize, SMEM2_TOT);

    // 1) split inputs (bf16 hi/lo)
    split_f32<<<(AN * AD / 4 + 255) / 256, 256>>>(x,  xh,  xl,  AN * AD / 4);
    split_f32<<<(AD * AD / 4 + 255) / 256, 256>>>(Wq, Wqh, Wql, AD * AD / 4);
    split_f32<<<(AD * AD / 4 + 255) / 256, 256>>>(Wk, Wkh, Wkl, AD * AD / 4);
    split_f32<<<(AD * AD / 4 + 255) / 256, 256>>>(Wv, Wvh, Wvl, AD * AD / 4);

    // 2) projections (bf16 3-pass, fp16 outputs)
    dim3 gP(AD / 256, AN / 128);
    hgemm_nt<4><<<gP, 512, SMEM_TOT>>>(xh, xl, Wqh, Wql, AN, AD, AD, Qf, nullptr);
    hgemm_nt<3><<<gP, 512, SMEM_TOT>>>(xh, xl, Wkh, Wkl, AN, AD, AD, Kfh, Kfl);
    dim3 gV(AN / 256, AD / 128);
    hgemm_nt<3><<<gV, 512, SMEM_TOT>>>(Wvh, Wvl, xh, xl, AD, AN, AD, Vth, Vtl);

    // 3) scores: fp16 2-pass (Q unsplit, K hi/lo), mask epilogue
    dim3 gS(AN / 256, AN / 128);
    hgemm2_f16<1><<<gS, 512, SMEM2_TOT>>>(Qf, Kfh, Kfl, AN, AN, AD,
                                          attn, mask, scale);

    // 4) softmax (+ fp16 P)
    softmax_rows<<<AN, 512, AN * sizeof(float)>>>(attn, P, AN);

    // 5) context: fp16 2-pass
    dim3 gC(AD / 256, AN / 128);
    hgemm2_f16<2><<<gC, 512, SMEM2_TOT>>>(P, Vth, Vtl, AN, AD, AN,
                                          cntx, nullptr, 1.f);
}

// round 16
// speedup vs baseline: 1.7955x; 1.1848x over previous
#include <cuda_runtime.h>
#include <cuda_bf16.h>
#include <cuda_fp16.h>
#include <math.h>
#include <stdint.h>

// ============================================================================
// LocalAttention, split-precision warp MMA.
//   split x,W -> hi/lo bf16
//   Q = x@Wq^T  (bf16 3-pass, fp16-unsplit epi)
//   K = x@Wk^T  (bf16 3-pass, fp16 hi/lo epi)
//   Vt = Wv@x^T (bf16 3-pass, fp16-unsplit epi)
//   attn = softmax(mask ? -1e9 : Q@K^T*s)  (fp16 2-pass, mask epi; fp32)
//   softmax emits P as single fp16
//   cntx = P @ Vt^T  (fp16 1-pass)
// Output: [cntx (N*D) | attn (N*N)].  Mask is int32.
// ============================================================================

#define AN 8192
#define AD 512

// ---- device-global scratch ----
__device__ __nv_bfloat16 g_xh [(size_t)AN * AD], g_xl [(size_t)AN * AD];
__device__ __nv_bfloat16 g_Wqh[(size_t)AD * AD], g_Wql[(size_t)AD * AD];
__device__ __nv_bfloat16 g_Wkh[(size_t)AD * AD], g_Wkl[(size_t)AD * AD];
__device__ __nv_bfloat16 g_Wvh[(size_t)AD * AD], g_Wvl[(size_t)AD * AD];
__device__ __half        g_Qf [(size_t)AN * AD];
__device__ __half        g_Kfh[(size_t)AN * AD], g_Kfl[(size_t)AN * AD];
__device__ __half        g_Vth[(size_t)AD * AN];
__device__ __half        g_P  [(size_t)AN * (size_t)AN];
__device__ float         g_S  [(size_t)AN * (size_t)AN];   // fallback attn scratch

// ---------------------------------------------------------------------------
// helpers
// ---------------------------------------------------------------------------
__device__ __forceinline__ uint32_t smem_u32(const void* p) {
    uint32_t a;
    asm("{ .reg .u64 t; cvta.to.shared.u64 t, %1; cvt.u32.u64 %0, t; }"
        : "=r"(a) : "l"(p));
    return a;
}
__device__ __forceinline__ void cp16(uint32_t dst, const void* src) {
    asm volatile("cp.async.cg.shared.global [%0], [%1], 16;" :: "r"(dst), "l"(src));
}
#define CP_COMMIT() asm volatile("cp.async.commit_group;" ::: "memory")
#define CP_WAIT(N)  asm volatile("cp.async.wait_group %0;" :: "n"(N) : "memory")

__device__ __forceinline__ void ldsm_x4(uint32_t* r, uint32_t addr) {
    asm volatile("ldmatrix.sync.aligned.m8n8.x4.shared.b16 {%0,%1,%2,%3}, [%4];"
                 : "=r"(r[0]), "=r"(r[1]), "=r"(r[2]), "=r"(r[3]) : "r"(addr));
}
__device__ __forceinline__ void mma16816(float* d, const uint32_t* a, const uint32_t* b) {
    asm volatile(
        "mma.sync.aligned.m16n8k16.row.col.f32.bf16.bf16.f32 "
        "{%0,%1,%2,%3}, {%4,%5,%6,%7}, {%8,%9}, {%0,%1,%2,%3};"
        : "+f"(d[0]), "+f"(d[1]), "+f"(d[2]), "+f"(d[3])
        : "r"(a[0]), "r"(a[1]), "r"(a[2]), "r"(a[3]), "r"(b[0]), "r"(b[1]));
}
__device__ __forceinline__ void mma16816h(float* d, const uint32_t* a, const uint32_t* b) {
    asm volatile(
        "mma.sync.aligned.m16n8k16.row.col.f32.f16.f16.f32 "
        "{%0,%1,%2,%3}, {%4,%5,%6,%7}, {%8,%9}, {%0,%1,%2,%3};"
        : "+f"(d[0]), "+f"(d[1]), "+f"(d[2]), "+f"(d[3])
        : "r"(a[0]), "r"(a[1]), "r"(a[2]), "r"(a[3]), "r"(b[0]), "r"(b[1]));
}
__device__ __forceinline__ void split1(float v, __nv_bfloat16& h, __nv_bfloat16& l) {
    h = __float2bfloat16_rn(v);
    l = __float2bfloat16_rn(v - __bfloat162float(h));
}
__device__ __forceinline__ void split1h(float v, __half& h, __half& l) {
    h = __float2half_rn(v);
    l = __float2half_rn(v - __half2float(h));
}

// 128B-row swizzle: 16B chunks c in 0..7, phys chunk = c ^ (row & 7).
__device__ __forceinline__ uint32_t swz(uint32_t row, uint32_t c) {
    return row * 128 + ((c ^ (row & 7)) << 4);
}

// ---------------------------------------------------------------------------
// split kernel: fp32 -> (hi, lo) bf16
// ---------------------------------------------------------------------------
__global__ __launch_bounds__(256)
void split_f32(const float* __restrict__ in, __nv_bfloat16* __restrict__ hi,
               __nv_bfloat16* __restrict__ lo, int n4)
{
    int i = blockIdx.x * 256 + threadIdx.x;
    if (i >= n4) return;
    float4 v = *(const float4*)(in + (size_t)i * 4);
    __nv_bfloat16 h0, h1, h2, h3, l0, l1, l2, l3;
    split1(v.x, h0, l0); split1(v.y, h1, l1);
    split1(v.z, h2, l2); split1(v.w, h3, l3);
    *(__nv_bfloat162*)(hi + (size_t)i * 4)     = __nv_bfloat162(h0, h1);
    *(__nv_bfloat162*)(hi + (size_t)i * 4 + 2) = __nv_bfloat162(h2, h3);
    *(__nv_bfloat162*)(lo + (size_t)i * 4)     = __nv_bfloat162(l0, l1);
    *(__nv_bfloat162*)(lo + (size_t)i * 4 + 2) = __nv_bfloat162(l2, l3);
}

// ---------------------------------------------------------------------------
// NT split-bf16 GEMM (3-pass): C = (Ah+Al)(Bh+Bl)^T.  Block 128x256x64,
// 512 threads, warp tile 32x64, 2-stage cp.async.
// EPI: 3 = split-fp16 out (Fhi/Flo), 4 = unsplit fp16 out (Fhi)
// ---------------------------------------------------------------------------
#define A_MAT  (128 * 128)
#define B_MAT  (256 * 128)
#define STAGEB (2 * A_MAT + 2 * B_MAT)     // 98304 B
#define SMEM_TOT (2 * STAGEB)              // 196608 B

template <int EPI>
__global__ __launch_bounds__(512)
void hgemm_nt(const __nv_bfloat16* __restrict__ Ah, const __nv_bfloat16* __restrict__ Al,
              const __nv_bfloat16* __restrict__ Bh, const __nv_bfloat16* __restrict__ Bl,
              int M, int Nn, int K,
              __half* __restrict__ Fhi, __half* __restrict__ Flo)
{
    extern __shared__ char smem[];
    const uint32_t sb = smem_u32(smem);
    const int tid = threadIdx.x;
    const int wid = tid >> 5, lid = tid & 31;
    const int mBase = blockIdx.y * 128;
    const int nBase = blockIdx.x * 256;
    const int mW = (wid & 3) * 32;
    const int nW = (wid >> 2) * 64;

    const __nv_bfloat16* gA[2] = { Ah + (size_t)mBase * K, Al + (size_t)mBase * K };
    const __nv_bfloat16* gB[2] = { Bh + (size_t)nBase * K, Bl + (size_t)nBase * K };

    float acc[2][8][4];
#pragma unroll
    for (int i = 0; i < 2; i++)
#pragma unroll
        for (int j = 0; j < 8; j++)
#pragma unroll
            for (int v = 0; v < 4; v++) acc[i][j][v] = 0.f;

    const int ntiles = K / 64;

    auto load_tile = [&](int kt, int s) {
        const uint32_t st = sb + s * STAGEB;
#pragma unroll
        for (int j = 0; j < 2; ++j) {
            int slot = tid + j * 512;
            int row = slot >> 3, c = slot & 7;
            size_t go = (size_t)row * K + kt * 64 + c * 8;
            uint32_t so = swz(row, c);
            cp16(st + 0 * A_MAT + so, gA[0] + go);
            cp16(st + 1 * A_MAT + so, gA[1] + go);
        }
#pragma unroll
        for (int j = 0; j < 4; ++j) {
            int slot = tid + j * 512;
            int row = slot >> 3, c = slot & 7;
            size_t go = (size_t)row * K + kt * 64 + c * 8;
            uint32_t so = swz(row, c);
            cp16(st + 2 * A_MAT + so,         gB[0] + go);
            cp16(st + 2 * A_MAT + B_MAT + so, gB[1] + go);
        }
        CP_COMMIT();
    };

    load_tile(0, 0);

    for (int kt = 0; kt < ntiles; ++kt) {
        if (kt + 1 < ntiles) {
            load_tile(kt + 1, (kt + 1) & 1);
            CP_WAIT(1);
        } else {
            CP_WAIT(0);
        }
        __syncthreads();

        const uint32_t st = sb + (kt & 1) * STAGEB;

#pragma unroll
        for (int s = 0; s < 4; ++s) {
            uint32_t ah[2][4], al[2][4];
            const uint32_t cA = s * 2 + (lid >> 4);
#pragma unroll
            for (int f = 0; f < 2; ++f) {
                uint32_t ra = st + swz(mW + f * 16 + (lid & 15), cA);
                ldsm_x4(ah[f], ra);
                ldsm_x4(al[f], ra + A_MAT);
            }
            const uint32_t rowB = ((lid >> 4) * 8) + (lid & 7);
            const uint32_t cB = s * 2 + ((lid >> 3) & 1);
#pragma unroll
            for (int half = 0; half < 2; ++half) {
                uint32_t bh[4][2], bl[4][2];
#pragma unroll
                for (int f = 0; f < 2; ++f) {
                    uint32_t rb = st + 2 * A_MAT +
                                  swz(nW + half * 32 + f * 16 + rowB, cB);
                    ldsm_x4(&bh[2 * f][0], rb);
                    ldsm_x4(&bl[2 * f][0], rb + B_MAT);
                }
#pragma unroll
                for (int mf = 0; mf < 2; ++mf)
#pragma unroll
                    for (int nf = 0; nf < 4; ++nf) {
                        float* d = acc[mf][half * 4 + nf];
                        mma16816(d, ah[mf], bh[nf]);
                        mma16816(d, ah[mf], bl[nf]);
                        mma16816(d, al[mf], bh[nf]);
                    }
            }
        }
        __syncthreads();
    }

    // ---- epilogue ----
    const int r0b = mBase + mW + (lid >> 2);
    const int c0b = nBase + nW + (lid & 3) * 2;
#pragma unroll
    for (int mf = 0; mf < 2; ++mf) {
#pragma unroll
        for (int nf = 0; nf < 8; ++nf) {
            const float* d = acc[mf][nf];
#pragma unroll
            for (int h = 0; h < 2; ++h) {
                int row = r0b + mf * 16 + h * 8;
                int col = c0b + nf * 8;
                size_t o = (size_t)row * Nn + col;
                float v0 = d[h * 2 + 0], v1 = d[h * 2 + 1];
                if (EPI == 3) {
                    __half h0, h1, l0, l1;
                    split1h(v0, h0, l0); split1h(v1, h1, l1);
                    *(__half2*)(Fhi + o) = __halves2half2(h0, h1);
                    *(__half2*)(Flo + o) = __halves2half2(l0, l1);
                } else {
                    *(__half2*)(Fhi + o) = __floats2half2_rn(v0, v1);
                }
            }
        }
    }
}

// ---------------------------------------------------------------------------
// NT fp16 GEMM: C[M,Nn] = A[M,K] * (Bh[+Bl])[Nn,K]^T, fp32 out.
// A unsplit fp16. Block 128x256x64, 512 threads, warp tile 32x64, 2-stage.
// EPI: 1 = mask+scale fp32, 2 = plain fp32.  NPASS: 1 (Bh only) or 2 (Bh+Bl).
// ---------------------------------------------------------------------------
#define STAGE2(NP) (A_MAT + (NP) * B_MAT)
#define SMEM2_TOT(NP) (2 * STAGE2(NP))

template <int EPI, int NPASS>
__global__ __launch_bounds__(512)
void hgemm2_f16(const __half* __restrict__ A,
                const __half* __restrict__ Bh, const __half* __restrict__ Bl,
                int M, int Nn, int K, float* __restrict__ Cf,
                const int* __restrict__ mask, float scale)
{
    extern __shared__ char smem[];
    const uint32_t sb = smem_u32(smem);
    const int tid = threadIdx.x;
    const int wid = tid >> 5, lid = tid & 31;
    const int mBase = blockIdx.y * 128;
    const int nBase = blockIdx.x * 256;
    const int mW = (wid & 3) * 32;
    const int nW = (wid >> 2) * 64;

    const __half* gA = A + (size_t)mBase * K;
    const __half* gB0 = Bh + (size_t)nBase * K;
    const __half* gB1 = (NPASS == 2) ? Bl + (size_t)nBase * K : nullptr;

    float acc[2][8][4];
#pragma unroll
    for (int i = 0; i < 2; i++)
#pragma unroll
        for (int j = 0; j < 8; j++)
#pragma unroll
            for (int v = 0; v < 4; v++) acc[i][j][v] = 0.f;

    const int ntiles = K / 64;

    auto load_tile = [&](int kt, int s) {
        const uint32_t st = sb + s * STAGE2(NPASS);
#pragma unroll
        for (int j = 0; j < 2; ++j) {
            int slot = tid + j * 512;
            int row = slot >> 3, c = slot & 7;
            size_t go = (size_t)row * K + kt * 64 + c * 8;
            cp16(st + swz(row, c), gA + go);
        }
#pragma unroll
        for (int j = 0; j < 4; ++j) {
            int slot = tid + j * 512;
            int row = slot >> 3, c = slot & 7;
            size_t go = (size_t)row * K + kt * 64 + c * 8;
            uint32_t so = swz(row, c);
            cp16(st + A_MAT + so, gB0 + go);
            if (NPASS == 2) cp16(st + A_MAT + B_MAT + so, gB1 + go);
        }
        CP_COMMIT();
    };

    load_tile(0, 0);

    for (int kt = 0; kt < ntiles; ++kt) {
        if (kt + 1 < ntiles) {
            load_tile(kt + 1, (kt + 1) & 1);
            CP_WAIT(1);
        } else {
            CP_WAIT(0);
        }
        __syncthreads();

        const uint32_t st = sb + (kt & 1) * STAGE2(NPASS);

#pragma unroll
        for (int s = 0; s < 4; ++s) {
            uint32_t ah[2][4];
            const uint32_t cA = s * 2 + (lid >> 4);
#pragma unroll
            for (int f = 0; f < 2; ++f)
                ldsm_x4(ah[f], st + swz(mW + f * 16 + (lid & 15), cA));

            const uint32_t rowB = ((lid >> 4) * 8) + (lid & 7);
            const uint32_t cB = s * 2 + ((lid >> 3) & 1);
#pragma unroll
            for (int half = 0; half < 2; ++half) {
                uint32_t bh[4][2], bl[4][2];
#pragma unroll
                for (int f = 0; f < 2; ++f) {
                    uint32_t rb = st + A_MAT +
                                  swz(nW + half * 32 + f * 16 + rowB, cB);
                    ldsm_x4(&bh[2 * f][0], rb);
                    if (NPASS == 2) ldsm_x4(&bl[2 * f][0], rb + B_MAT);
                }
#pragma unroll
                for (int mf = 0; mf < 2; ++mf)
#pragma unroll
                    for (int nf = 0; nf < 4; ++nf) {
                        float* d = acc[mf][half * 4 + nf];
                        mma16816h(d, ah[mf], bh[nf]);
                        if (NPASS == 2) mma16816h(d, ah[mf], bl[nf]);
                    }
            }
        }
        __syncthreads();
    }

    const int r0b = mBase + mW + (lid >> 2);
    const int c0b = nBase + nW + (lid & 3) * 2;
#pragma unroll
    for (int mf = 0; mf < 2; ++mf)
#pragma unroll
        for (int nf = 0; nf < 8; ++nf) {
            const float* d = acc[mf][nf];
#pragma unroll
            for (int h = 0; h < 2; ++h) {
                int row = r0b + mf * 16 + h * 8;
                int col = c0b + nf * 8;
                size_t o = (size_t)row * Nn + col;
                float v0 = d[h * 2 + 0], v1 = d[h * 2 + 1];
                if (EPI == 1) {
                    int2 mv = *(const int2*)(mask + o);
                    float2 w;
                    w.x = mv.x ? -1e9f : v0 * scale;
                    w.y = mv.y ? -1e9f : v1 * scale;
                    *(float2*)(Cf + o) = w;
                } else {
                    *(float2*)(Cf + o) = make_float2(v0, v1);
                }
            }
        }
}

// ---------------------------------------------------------------------------
// Row softmax (in place, fp32) + emit P as single fp16.  512 threads/row.
// ---------------------------------------------------------------------------
__global__ __launch_bounds__(512)
void softmax_rows(float* __restrict__ S, __half* __restrict__ P, int n)
{
    extern __shared__ float row[];
    __shared__ float red[17];

    const int tid = threadIdx.x;
    float* p = S + (size_t)blockIdx.x * n;
    __half* ph = P + (size_t)blockIdx.x * n;

    float m = -INFINITY;
    for (int i = tid * 4; i < n; i += 2048) {
        float4 v = *(const float4*)(p + i);
        *(float4*)(row + i) = v;
        m = fmaxf(m, fmaxf(fmaxf(v.x, v.y), fmaxf(v.z, v.w)));
    }
#pragma unroll
    for (int o = 16; o; o >>= 1) m = fmaxf(m, __shfl_xor_sync(~0u, m, o));
    if ((tid & 31) == 0) red[tid >> 5] = m;
    __syncthreads();
    if (tid < 32) {
        float v = (tid < 16) ? red[tid] : -INFINITY;
#pragma unroll
        for (int o = 8; o; o >>= 1) v = fmaxf(v, __shfl_xor_sync(~0u, v, o));
        if (tid == 0) red[16] = v;
    }
    __syncthreads();
    m = red[16];

    float s = 0.f;
    for (int i = tid * 4; i < n; i += 2048) {
        float4 v = *(float4*)(row + i);
        v.x = __expf(v.x - m); v.y = __expf(v.y - m);
        v.z = __expf(v.z - m); v.w = __expf(v.w - m);
        s += (v.x + v.y) + (v.z + v.w);
        *(float4*)(row + i) = v;
    }
    __syncthreads();
#pragma unroll
    for (int o = 16; o; o >>= 1) s += __shfl_xor_sync(~0u, s, o);
    if ((tid & 31) == 0) red[tid >> 5] = s;
    __syncthreads();
    if (tid < 32) {
        float v = (tid < 16) ? red[tid] : 0.f;
#pragma unroll
        for (int o = 8; o; o >>= 1) v += __shfl_xor_sync(~0u, v, o);
        if (tid == 0) red[16] = v;
    }
    __syncthreads();
    const float inv = 1.f / red[16];

    for (int i = tid * 4; i < n; i += 2048) {
        float4 v = *(float4*)(row + i);
        v.x *= inv; v.y *= inv; v.z *= inv; v.w *= inv;
        *(float4*)(p + i) = v;
        *(__half2*)(ph + i)     = __floats2half2_rn(v.x, v.y);
        *(__half2*)(ph + i + 2) = __floats2half2_rn(v.z, v.w);
    }
}

// ---------------------------------------------------------------------------
// Launch
// ---------------------------------------------------------------------------
extern "C" void kernel_launch(void* const* d_in, const int* in_sizes, int n_in,
                              void* d_out, int out_size)
{
    const float* x    = (const float*)d_in[0];
    const int*   mask = (const int*)d_in[1];
    const float* Wq   = (const float*)d_in[2];
    const float* Wk   = (const float*)d_in[3];
    const float* Wv   = (const float*)d_in[4];
    float* out = (float*)d_out;

    __nv_bfloat16 *xh, *xl, *Wqh, *Wql, *Wkh, *Wkl, *Wvh, *Wvl;
    __half *Qf, *Kfh, *Kfl, *Vth, *P;
    cudaGetSymbolAddress((void**)&xh,  g_xh);  cudaGetSymbolAddress((void**)&xl,  g_xl);
    cudaGetSymbolAddress((void**)&Wqh, g_Wqh); cudaGetSymbolAddress((void**)&Wql, g_Wql);
    cudaGetSymbolAddress((void**)&Wkh, g_Wkh); cudaGetSymbolAddress((void**)&Wkl, g_Wkl);
    cudaGetSymbolAddress((void**)&Wvh, g_Wvh); cudaGetSymbolAddress((void**)&Wvl, g_Wvl);
    cudaGetSymbolAddress((void**)&Qf,  g_Qf);
    cudaGetSymbolAddress((void**)&Kfh, g_Kfh); cudaGetSymbolAddress((void**)&Kfl, g_Kfl);
    cudaGetSymbolAddress((void**)&Vth, g_Vth);
    cudaGetSymbolAddress((void**)&P,   g_P);

    const size_t nd = (size_t)AN * AD;
    const size_t nn = (size_t)AN * AN;
    float* cntx = out;
    float* attn = out + nd;
    if ((size_t)out_size < nd + nn)
        cudaGetSymbolAddress((void**)&attn, g_S);

    const float scale = 1.0f / sqrtf((float)AD);

    cudaFuncSetAttribute(hgemm_nt<3>, cudaFuncAttributeMaxDynamicSharedMemorySize, SMEM_TOT);
    cudaFuncSetAttribute(hgemm_nt<4>, cudaFuncAttributeMaxDynamicSharedMemorySize, SMEM_TOT);
    cudaFuncSetAttribute(hgemm2_f16<1, 2>, cudaFuncAttributeMaxDynamicSharedMemorySize, SMEM2_TOT(2));
    cudaFuncSetAttribute(hgemm2_f16<2, 1>, cudaFuncAttributeMaxDynamicSharedMemorySize, SMEM2_TOT(1));

    // 1) split inputs (bf16 hi/lo)
    split_f32<<<(AN * AD / 4 + 255) / 256, 256>>>(x,  xh,  xl,  AN * AD / 4);
    split_f32<<<(AD * AD / 4 + 255) / 256, 256>>>(Wq, Wqh, Wql, AD * AD / 4);
    split_f32<<<(AD * AD / 4 + 255) / 256, 256>>>(Wk, Wkh, Wkl, AD * AD / 4);
    split_f32<<<(AD * AD / 4 + 255) / 256, 256>>>(Wv, Wvh, Wvl, AD * AD / 4);

    // 2) projections (bf16 3-pass, fp16 outputs)
    dim3 gP(AD / 256, AN / 128);
    hgemm_nt<4><<<gP, 512, SMEM_TOT>>>(xh, xl, Wqh, Wql, AN, AD, AD, Qf, nullptr);
    hgemm_nt<3><<<gP, 512, SMEM_TOT>>>(xh, xl, Wkh, Wkl, AN, AD, AD, Kfh, Kfl);
    dim3 gV(AN / 256, AD / 128);
    hgemm_nt<4><<<gV, 512, SMEM_TOT>>>(Wvh, Wvl, xh, xl, AD, AN, AD, Vth, nullptr);

    // 3) scores: fp16 2-pass (Q unsplit, K hi/lo), mask epilogue
    dim3 gS(AN / 256, AN / 128);
    hgemm2_f16<1, 2><<<gS, 512, SMEM2_TOT(2)>>>(Qf, Kfh, Kfl, AN, AN, AD,
                                                attn, mask, scale);

    // 4) softmax (+ fp16 P)
    softmax_rows<<<AN, 512, AN * sizeof(float)>>>(attn, P, AN);

    // 5) context: fp16 1-pass
    dim3 gC(AD / 256, AN / 128);
    hgemm2_f16<2, 1><<<gC, 512, SMEM2_TOT(1)>>>(P, Vth, nullptr, AN, AD, AN,
                                                cntx, nullptr, 1.f);
}

// round 17
// speedup vs baseline: 2.1507x; 1.1978x over previous
#include <cuda_runtime.h>
#include <cuda_bf16.h>
#include <cuda_fp16.h>
#include <math.h>
#include <stdint.h>

// ============================================================================
// LocalAttention, split-precision warp MMA.
//   split x,W -> hi/lo bf16
//   Q = x@Wq^T, K = x@Wk^T, Vt = Wv@x^T  (bf16 3-pass, fp16-unsplit epi)
//   attn = softmax(mask ? -1e9 : Q@K^T*s)  (fp16 1-pass, mask epi; fp32)
//   softmax emits P as single fp16
//   cntx = P @ Vt^T  (fp16 1-pass)
// Output: [cntx (N*D) | attn (N*N)].  Mask is int32.
// ============================================================================

#define AN 8192
#define AD 512

// ---- device-global scratch ----
__device__ __nv_bfloat16 g_xh [(size_t)AN * AD], g_xl [(size_t)AN * AD];
__device__ __nv_bfloat16 g_Wqh[(size_t)AD * AD], g_Wql[(size_t)AD * AD];
__device__ __nv_bfloat16 g_Wkh[(size_t)AD * AD], g_Wkl[(size_t)AD * AD];
__device__ __nv_bfloat16 g_Wvh[(size_t)AD * AD], g_Wvl[(size_t)AD * AD];
__device__ __half        g_Qf [(size_t)AN * AD];
__device__ __half        g_Kf [(size_t)AN * AD];
__device__ __half        g_Vth[(size_t)AD * AN];
__device__ __half        g_P  [(size_t)AN * (size_t)AN];
__device__ float         g_S  [(size_t)AN * (size_t)AN];   // fallback attn scratch

// ---------------------------------------------------------------------------
// helpers
// ---------------------------------------------------------------------------
__device__ __forceinline__ uint32_t smem_u32(const void* p) {
    uint32_t a;
    asm("{ .reg .u64 t; cvta.to.shared.u64 t, %1; cvt.u32.u64 %0, t; }"
        : "=r"(a) : "l"(p));
    return a;
}
__device__ __forceinline__ void cp16(uint32_t dst, const void* src) {
    asm volatile("cp.async.cg.shared.global [%0], [%1], 16;" :: "r"(dst), "l"(src));
}
#define CP_COMMIT() asm volatile("cp.async.commit_group;" ::: "memory")
#define CP_WAIT(N)  asm volatile("cp.async.wait_group %0;" :: "n"(N) : "memory")

__device__ __forceinline__ void ldsm_x4(uint32_t* r, uint32_t addr) {
    asm volatile("ldmatrix.sync.aligned.m8n8.x4.shared.b16 {%0,%1,%2,%3}, [%4];"
                 : "=r"(r[0]), "=r"(r[1]), "=r"(r[2]), "=r"(r[3]) : "r"(addr));
}
__device__ __forceinline__ void mma16816(float* d, const uint32_t* a, const uint32_t* b) {
    asm volatile(
        "mma.sync.aligned.m16n8k16.row.col.f32.bf16.bf16.f32 "
        "{%0,%1,%2,%3}, {%4,%5,%6,%7}, {%8,%9}, {%0,%1,%2,%3};"
        : "+f"(d[0]), "+f"(d[1]), "+f"(d[2]), "+f"(d[3])
        : "r"(a[0]), "r"(a[1]), "r"(a[2]), "r"(a[3]), "r"(b[0]), "r"(b[1]));
}
__device__ __forceinline__ void mma16816h(float* d, const uint32_t* a, const uint32_t* b) {
    asm volatile(
        "mma.sync.aligned.m16n8k16.row.col.f32.f16.f16.f32 "
        "{%0,%1,%2,%3}, {%4,%5,%6,%7}, {%8,%9}, {%0,%1,%2,%3};"
        : "+f"(d[0]), "+f"(d[1]), "+f"(d[2]), "+f"(d[3])
        : "r"(a[0]), "r"(a[1]), "r"(a[2]), "r"(a[3]), "r"(b[0]), "r"(b[1]));
}
__device__ __forceinline__ void split1(float v, __nv_bfloat16& h, __nv_bfloat16& l) {
    h = __float2bfloat16_rn(v);
    l = __float2bfloat16_rn(v - __bfloat162float(h));
}

// 128B-row swizzle: 16B chunks c in 0..7, phys chunk = c ^ (row & 7).
__device__ __forceinline__ uint32_t swz(uint32_t row, uint32_t c) {
    return row * 128 + ((c ^ (row & 7)) << 4);
}

// ---------------------------------------------------------------------------
// split kernel: fp32 -> (hi, lo) bf16
// ---------------------------------------------------------------------------
__global__ __launch_bounds__(256)
void split_f32(const float* __restrict__ in, __nv_bfloat16* __restrict__ hi,
               __nv_bfloat16* __restrict__ lo, int n4)
{
    int i = blockIdx.x * 256 + threadIdx.x;
    if (i >= n4) return;
    float4 v = *(const float4*)(in + (size_t)i * 4);
    __nv_bfloat16 h0, h1, h2, h3, l0, l1, l2, l3;
    split1(v.x, h0, l0); split1(v.y, h1, l1);
    split1(v.z, h2, l2); split1(v.w, h3, l3);
    *(__nv_bfloat162*)(hi + (size_t)i * 4)     = __nv_bfloat162(h0, h1);
    *(__nv_bfloat162*)(hi + (size_t)i * 4 + 2) = __nv_bfloat162(h2, h3);
    *(__nv_bfloat162*)(lo + (size_t)i * 4)     = __nv_bfloat162(l0, l1);
    *(__nv_bfloat162*)(lo + (size_t)i * 4 + 2) = __nv_bfloat162(l2, l3);
}

// ---------------------------------------------------------------------------
// NT split-bf16 GEMM (3-pass): C = (Ah+Al)(Bh+Bl)^T.  Block 128x256x64,
// 512 threads, warp tile 32x64, 2-stage cp.async.  Emits unsplit fp16.
// ---------------------------------------------------------------------------
#define A_MAT  (128 * 128)
#define B_MAT  (256 * 128)
#define STAGEB (2 * A_MAT + 2 * B_MAT)     // 98304 B
#define SMEM_TOT (2 * STAGEB)              // 196608 B

__global__ __launch_bounds__(512)
void hgemm_nt(const __nv_bfloat16* __restrict__ Ah, const __nv_bfloat16* __restrict__ Al,
              const __nv_bfloat16* __restrict__ Bh, const __nv_bfloat16* __restrict__ Bl,
              int M, int Nn, int K, __half* __restrict__ Fhi)
{
    extern __shared__ char smem[];
    const uint32_t sb = smem_u32(smem);
    const int tid = threadIdx.x;
    const int wid = tid >> 5, lid = tid & 31;
    const int mBase = blockIdx.y * 128;
    const int nBase = blockIdx.x * 256;
    const int mW = (wid & 3) * 32;
    const int nW = (wid >> 2) * 64;

    const __nv_bfloat16* gA[2] = { Ah + (size_t)mBase * K, Al + (size_t)mBase * K };
    const __nv_bfloat16* gB[2] = { Bh + (size_t)nBase * K, Bl + (size_t)nBase * K };

    float acc[2][8][4];
#pragma unroll
    for (int i = 0; i < 2; i++)
#pragma unroll
        for (int j = 0; j < 8; j++)
#pragma unroll
            for (int v = 0; v < 4; v++) acc[i][j][v] = 0.f;

    const int ntiles = K / 64;

    auto load_tile = [&](int kt, int s) {
        const uint32_t st = sb + s * STAGEB;
#pragma unroll
        for (int j = 0; j < 2; ++j) {
            int slot = tid + j * 512;
            int row = slot >> 3, c = slot & 7;
            size_t go = (size_t)row * K + kt * 64 + c * 8;
            uint32_t so = swz(row, c);
            cp16(st + 0 * A_MAT + so, gA[0] + go);
            cp16(st + 1 * A_MAT + so, gA[1] + go);
        }
#pragma unroll
        for (int j = 0; j < 4; ++j) {
            int slot = tid + j * 512;
            int row = slot >> 3, c = slot & 7;
            size_t go = (size_t)row * K + kt * 64 + c * 8;
            uint32_t so = swz(row, c);
            cp16(st + 2 * A_MAT + so,         gB[0] + go);
            cp16(st + 2 * A_MAT + B_MAT + so, gB[1] + go);
        }
        CP_COMMIT();
    };

    load_tile(0, 0);

    for (int kt = 0; kt < ntiles; ++kt) {
        if (kt + 1 < ntiles) {
            load_tile(kt + 1, (kt + 1) & 1);
            CP_WAIT(1);
        } else {
            CP_WAIT(0);
        }
        __syncthreads();

        const uint32_t st = sb + (kt & 1) * STAGEB;

#pragma unroll
        for (int s = 0; s < 4; ++s) {
            uint32_t ah[2][4], al[2][4];
            const uint32_t cA = s * 2 + (lid >> 4);
#pragma unroll
            for (int f = 0; f < 2; ++f) {
                uint32_t ra = st + swz(mW + f * 16 + (lid & 15), cA);
                ldsm_x4(ah[f], ra);
                ldsm_x4(al[f], ra + A_MAT);
            }
            const uint32_t rowB = ((lid >> 4) * 8) + (lid & 7);
            const uint32_t cB = s * 2 + ((lid >> 3) & 1);
#pragma unroll
            for (int half = 0; half < 2; ++half) {
                uint32_t bh[4][2], bl[4][2];
#pragma unroll
                for (int f = 0; f < 2; ++f) {
                    uint32_t rb = st + 2 * A_MAT +
                                  swz(nW + half * 32 + f * 16 + rowB, cB);
                    ldsm_x4(&bh[2 * f][0], rb);
                    ldsm_x4(&bl[2 * f][0], rb + B_MAT);
                }
#pragma unroll
                for (int mf = 0; mf < 2; ++mf)
#pragma unroll
                    for (int nf = 0; nf < 4; ++nf) {
                        float* d = acc[mf][half * 4 + nf];
                        mma16816(d, ah[mf], bh[nf]);
                        mma16816(d, ah[mf], bl[nf]);
                        mma16816(d, al[mf], bh[nf]);
                    }
            }
        }
        __syncthreads();
    }

    // ---- epilogue: unsplit fp16 ----
    const int r0b = mBase + mW + (lid >> 2);
    const int c0b = nBase + nW + (lid & 3) * 2;
#pragma unroll
    for (int mf = 0; mf < 2; ++mf)
#pragma unroll
        for (int nf = 0; nf < 8; ++nf) {
            const float* d = acc[mf][nf];
#pragma unroll
            for (int h = 0; h < 2; ++h) {
                int row = r0b + mf * 16 + h * 8;
                int col = c0b + nf * 8;
                size_t o = (size_t)row * Nn + col;
                *(__half2*)(Fhi + o) = __floats2half2_rn(d[h * 2], d[h * 2 + 1]);
            }
        }
}

// ---------------------------------------------------------------------------
// NT fp16 1-pass GEMM: C[M,Nn] = A[M,K] * B[Nn,K]^T, fp32 out.
// Block 128x256x64, 512 threads, warp tile 32x64, 2-stage.
// EPI: 1 = mask+scale fp32, 2 = plain fp32.
// ---------------------------------------------------------------------------
#define STAGE2 (A_MAT + B_MAT)             // 49152 B (A|B)
#define SMEM2_TOT (2 * STAGE2)             // 98304 B

template <int EPI>
__global__ __launch_bounds__(512)
void hgemm1_f16(const __half* __restrict__ A, const __half* __restrict__ B,
                int M, int Nn, int K, float* __restrict__ Cf,
                const int* __restrict__ mask, float scale)
{
    extern __shared__ char smem[];
    const uint32_t sb = smem_u32(smem);
    const int tid = threadIdx.x;
    const int wid = tid >> 5, lid = tid & 31;
    const int mBase = blockIdx.y * 128;
    const int nBase = blockIdx.x * 256;
    const int mW = (wid & 3) * 32;
    const int nW = (wid >> 2) * 64;

    const __half* gA = A + (size_t)mBase * K;
    const __half* gB = B + (size_t)nBase * K;

    float acc[2][8][4];
#pragma unroll
    for (int i = 0; i < 2; i++)
#pragma unroll
        for (int j = 0; j < 8; j++)
#pragma unroll
            for (int v = 0; v < 4; v++) acc[i][j][v] = 0.f;

    const int ntiles = K / 64;

    auto load_tile = [&](int kt, int s) {
        const uint32_t st = sb + s * STAGE2;
#pragma unroll
        for (int j = 0; j < 2; ++j) {
            int slot = tid + j * 512;
            int row = slot >> 3, c = slot & 7;
            size_t go = (size_t)row * K + kt * 64 + c * 8;
            cp16(st + swz(row, c), gA + go);
        }
#pragma unroll
        for (int j = 0; j < 4; ++j) {
            int slot = tid + j * 512;
            int row = slot >> 3, c = slot & 7;
            size_t go = (size_t)row * K + kt * 64 + c * 8;
            cp16(st + A_MAT + swz(row, c), gB + go);
        }
        CP_COMMIT();
    };

    load_tile(0, 0);

    for (int kt = 0; kt < ntiles; ++kt) {
        if (kt + 1 < ntiles) {
            load_tile(kt + 1, (kt + 1) & 1);
            CP_WAIT(1);
        } else {
            CP_WAIT(0);
        }
        __syncthreads();

        const uint32_t st = sb + (kt & 1) * STAGE2;

#pragma unroll
        for (int s = 0; s < 4; ++s) {
            uint32_t ah[2][4];
            const uint32_t cA = s * 2 + (lid >> 4);
#pragma unroll
            for (int f = 0; f < 2; ++f)
                ldsm_x4(ah[f], st + swz(mW + f * 16 + (lid & 15), cA));

            const uint32_t rowB = ((lid >> 4) * 8) + (lid & 7);
            const uint32_t cB = s * 2 + ((lid >> 3) & 1);
#pragma unroll
            for (int half = 0; half < 2; ++half) {
                uint32_t bh[4][2];
#pragma unroll
                for (int f = 0; f < 2; ++f) {
                    uint32_t rb = st + A_MAT +
                                  swz(nW + half * 32 + f * 16 + rowB, cB);
                    ldsm_x4(&bh[2 * f][0], rb);
                }
#pragma unroll
                for (int mf = 0; mf < 2; ++mf)
#pragma unroll
                    for (int nf = 0; nf < 4; ++nf)
                        mma16816h(acc[mf][half * 4 + nf], ah[mf], bh[nf]);
            }
        }
        __syncthreads();
    }

    const int r0b = mBase + mW + (lid >> 2);
    const int c0b = nBase + nW + (lid & 3) * 2;
#pragma unroll
    for (int mf = 0; mf < 2; ++mf)
#pragma unroll
        for (int nf = 0; nf < 8; ++nf) {
            const float* d = acc[mf][nf];
#pragma unroll
            for (int h = 0; h < 2; ++h) {
                int row = r0b + mf * 16 + h * 8;
                int col = c0b + nf * 8;
                size_t o = (size_t)row * Nn + col;
                float v0 = d[h * 2 + 0], v1 = d[h * 2 + 1];
                if (EPI == 1) {
                    int2 mv = *(const int2*)(mask + o);
                    float2 w;
                    w.x = mv.x ? -1e9f : v0 * scale;
                    w.y = mv.y ? -1e9f : v1 * scale;
                    *(float2*)(Cf + o) = w;
                } else {
                    *(float2*)(Cf + o) = make_float2(v0, v1);
                }
            }
        }
}

// ---------------------------------------------------------------------------
// Row softmax (in place, fp32) + emit P as single fp16.  512 threads/row.
// ---------------------------------------------------------------------------
__global__ __launch_bounds__(512)
void softmax_rows(float* __restrict__ S, __half* __restrict__ P, int n)
{
    extern __shared__ float row[];
    __shared__ float red[17];

    const int tid = threadIdx.x;
    float* p = S + (size_t)blockIdx.x * n;
    __half* ph = P + (size_t)blockIdx.x * n;

    float m = -INFINITY;
    for (int i = tid * 4; i < n; i += 2048) {
        float4 v = *(const float4*)(p + i);
        *(float4*)(row + i) = v;
        m = fmaxf(m, fmaxf(fmaxf(v.x, v.y), fmaxf(v.z, v.w)));
    }
#pragma unroll
    for (int o = 16; o; o >>= 1) m = fmaxf(m, __shfl_xor_sync(~0u, m, o));
    if ((tid & 31) == 0) red[tid >> 5] = m;
    __syncthreads();
    if (tid < 32) {
        float v = (tid < 16) ? red[tid] : -INFINITY;
#pragma unroll
        for (int o = 8; o; o >>= 1) v = fmaxf(v, __shfl_xor_sync(~0u, v, o));
        if (tid == 0) red[16] = v;
    }
    __syncthreads();
    m = red[16];

    float s = 0.f;
    for (int i = tid * 4; i < n; i += 2048) {
        float4 v = *(float4*)(row + i);
        v.x = __expf(v.x - m); v.y = __expf(v.y - m);
        v.z = __expf(v.z - m); v.w = __expf(v.w - m);
        s += (v.x + v.y) + (v.z + v.w);
        *(float4*)(row + i) = v;
    }
    __syncthreads();
#pragma unroll
    for (int o = 16; o; o >>= 1) s += __shfl_xor_sync(~0u, s, o);
    if ((tid & 31) == 0) red[tid >> 5] = s;
    __syncthreads();
    if (tid < 32) {
        float v = (tid < 16) ? red[tid] : 0.f;
#pragma unroll
        for (int o = 8; o; o >>= 1) v += __shfl_xor_sync(~0u, v, o);
        if (tid == 0) red[16] = v;
    }
    __syncthreads();
    const float inv = 1.f / red[16];

    for (int i = tid * 4; i < n; i += 2048) {
        float4 v = *(float4*)(row + i);
        v.x *= inv; v.y *= inv; v.z *= inv; v.w *= inv;
        *(float4*)(p + i) = v;
        *(__half2*)(ph + i)     = __floats2half2_rn(v.x, v.y);
        *(__half2*)(ph + i + 2) = __floats2half2_rn(v.z, v.w);
    }
}

// ---------------------------------------------------------------------------
// Launch
// ---------------------------------------------------------------------------
extern "C" void kernel_launch(void* const* d_in, const int* in_sizes, int n_in,
                              void* d_out, int out_size)
{
    const float* x    = (const float*)d_in[0];
    const int*   mask = (const int*)d_in[1];
    const float* Wq   = (const float*)d_in[2];
    const float* Wk   = (const float*)d_in[3];
    const float* Wv   = (const float*)d_in[4];
    float* out = (float*)d_out;

    __nv_bfloat16 *xh, *xl, *Wqh, *Wql, *Wkh, *Wkl, *Wvh, *Wvl;
    __half *Qf, *Kf, *Vth, *P;
    cudaGetSymbolAddress((void**)&xh,  g_xh);  cudaGetSymbolAddress((void**)&xl,  g_xl);
    cudaGetSymbolAddress((void**)&Wqh, g_Wqh); cudaGetSymbolAddress((void**)&Wql, g_Wql);
    cudaGetSymbolAddress((void**)&Wkh, g_Wkh); cudaGetSymbolAddress((void**)&Wkl, g_Wkl);
    cudaGetSymbolAddress((void**)&Wvh, g_Wvh); cudaGetSymbolAddress((void**)&Wvl, g_Wvl);
    cudaGetSymbolAddress((void**)&Qf,  g_Qf);
    cudaGetSymbolAddress((void**)&Kf,  g_Kf);
    cudaGetSymbolAddress((void**)&Vth, g_Vth);
    cudaGetSymbolAddress((void**)&P,   g_P);

    const size_t nd = (size_t)AN * AD;
    const size_t nn = (size_t)AN * AN;
    float* cntx = out;
    float* attn = out + nd;
    if ((size_t)out_size < nd + nn)
        cudaGetSymbolAddress((void**)&attn, g_S);

    const float scale = 1.0f / sqrtf((float)AD);

    cudaFuncSetAttribute(hgemm_nt,      cudaFuncAttributeMaxDynamicSharedMemorySize, SMEM_TOT);
    cudaFuncSetAttribute(hgemm1_f16<1>, cudaFuncAttributeMaxDynamicSharedMemorySize, SMEM2_TOT);
    cudaFuncSetAttribute(hgemm1_f16<2>, cudaFuncAttributeMaxDynamicSharedMemorySize, SMEM2_TOT);

    // 1) split inputs (bf16 hi/lo)
    split_f32<<<(AN * AD / 4 + 255) / 256, 256>>>(x,  xh,  xl,  AN * AD / 4);
    split_f32<<<(AD * AD / 4 + 255) / 256, 256>>>(Wq, Wqh, Wql, AD * AD / 4);
    split_f32<<<(AD * AD / 4 + 255) / 256, 256>>>(Wk, Wkh, Wkl, AD * AD / 4);
    split_f32<<<(AD * AD / 4 + 255) / 256, 256>>>(Wv, Wvh, Wvl, AD * AD / 4);

    // 2) projections (bf16 3-pass, unsplit fp16 outputs)
    dim3 gP(AD / 256, AN / 128);
    hgemm_nt<<<gP, 512, SMEM_TOT>>>(xh, xl, Wqh, Wql, AN, AD, AD, Qf);
    hgemm_nt<<<gP, 512, SMEM_TOT>>>(xh, xl, Wkh, Wkl, AN, AD, AD, Kf);
    dim3 gV(AN / 256, AD / 128);
    hgemm_nt<<<gV, 512, SMEM_TOT>>>(Wvh, Wvl, xh, xl, AD, AN, AD, Vth);

    // 3) scores: fp16 1-pass (Q, K unsplit), mask epilogue
    dim3 gS(AN / 256, AN / 128);
    hgemm1_f16<1><<<gS, 512, SMEM2_TOT>>>(Qf, Kf, AN, AN, AD, attn, mask, scale);

    // 4) softmax (+ fp16 P)
    softmax_rows<<<AN, 512, AN * sizeof(float)>>>(attn, P, AN);

    // 5) context: fp16 1-pass
    dim3 gC(AD / 256, AN / 128);
    hgemm1_f16<2><<<gC, 512, SMEM2_TOT>>>(P, Vth, AN, AD, AN, cntx, nullptr, 1.f);
}